// round 1
// baseline (speedup 1.0000x reference)
#include <cuda_runtime.h>

#define NN 50000
#define F1 256
#define F2 128

// -------- scratch (static device globals; no allocation) --------
__device__ __align__(16) float g_deg[NN];
__device__ __align__(16) float g_dinv[NN];
__device__ __align__(16) float g_hs1[(size_t)NN * F1];   // (x@W1)*dinv, then h1 in-place
__device__ __align__(16) float g_acc1[(size_t)NN * F1];
__device__ __align__(16) float g_hs2[(size_t)NN * F2];
__device__ __align__(16) float g_acc2[(size_t)NN * F2];
__device__ int g_is64;

// -------- edge dtype detection (int64 vs int32) --------
// If edge_index is int64 (values < 50000), every odd 32-bit word of the buffer is 0.
// If int32 random in [0,50000), that is impossible over 4096 consecutive words.
__global__ void k_detect(const int* __restrict__ w, int nwords) {
    __shared__ int ok;
    if (threadIdx.x == 0) ok = 1;
    __syncthreads();
    for (int i = threadIdx.x; i < nwords / 2; i += blockDim.x)
        if (w[2 * i + 1] != 0) ok = 0;   // benign race
    __syncthreads();
    if (threadIdx.x == 0) g_is64 = ok;
}

__device__ __forceinline__ long long edge_at(const void* p, int i, int is64) {
    if (is64) return ((const long long*)p)[i];
    return (long long)((const int*)p)[i];
}

// -------- init --------
__global__ void k_setones(float* __restrict__ p, int n) {
    int i = blockIdx.x * blockDim.x + threadIdx.x;
    if (i < n) p[i] = 1.0f;   // self-loop contribution to degree
}
__global__ void k_zero4(float4* __restrict__ p, int n4) {
    int i = blockIdx.x * blockDim.x + threadIdx.x;
    if (i < n4) p[i] = make_float4(0.f, 0.f, 0.f, 0.f);
}

// -------- degree + rsqrt --------
__global__ void k_edgedeg(const void* __restrict__ ei, float* __restrict__ deg, int E) {
    int i = blockIdx.x * blockDim.x + threadIdx.x;
    if (i >= E) return;
    int is64 = g_is64;
    long long d = edge_at(ei, E + i, is64);   // dst = second row
    atomicAdd(deg + d, 1.0f);
}
__global__ void k_rsqrt(const float* __restrict__ deg, float* __restrict__ dinv, int n) {
    int i = blockIdx.x * blockDim.x + threadIdx.x;
    if (i < n) dinv[i] = rsqrtf(deg[i]);
}

// -------- GEMM: C[row] = (A@B)[row] * dinv[row]   (A:[M,K] B:[K,N] row-major) --------
// 128x128 tile, BK=16, 256 threads, 8x8 per thread (split 4+4 rows / 4+4 cols for
// conflict-free float4 LDS).
__global__ __launch_bounds__(256) void k_gemm(
    const float* __restrict__ A, const float* __restrict__ B,
    const float* __restrict__ dinv, float* __restrict__ C,
    int M, int N, int K)
{
    __shared__ float As[16][128];   // transposed: As[k][m]
    __shared__ float Bs[16][128];
    int tid = threadIdx.x;
    int tx = tid & 15;
    int ty = tid >> 4;
    int row0 = blockIdx.y * 128;
    int col0 = blockIdx.x * 128;

    float acc[8][8];
#pragma unroll
    for (int i = 0; i < 8; i++)
#pragma unroll
        for (int j = 0; j < 8; j++) acc[i][j] = 0.f;

    for (int kt = 0; kt < K; kt += 16) {
        // A tile: 128 rows x 16 k-cols = 512 float4, transposed on store
#pragma unroll
        for (int i = 0; i < 2; i++) {
            int f = tid * 2 + i;          // 0..511
            int r = f >> 2;               // 0..127
            int c = (f & 3) * 4;          // 0,4,8,12
            float4 v = make_float4(0.f, 0.f, 0.f, 0.f);
            int grow = row0 + r;
            if (grow < M) v = *(const float4*)(A + (size_t)grow * K + kt + c);
            As[c + 0][r] = v.x; As[c + 1][r] = v.y;
            As[c + 2][r] = v.z; As[c + 3][r] = v.w;
        }
        // B tile: 16 k-rows x 128 cols = 512 float4
#pragma unroll
        for (int i = 0; i < 2; i++) {
            int f = tid * 2 + i;
            int r = f >> 5;               // 0..15
            int c = (f & 31) * 4;         // 0..124
            *(float4*)&Bs[r][c] = *(const float4*)(B + (size_t)(kt + r) * N + col0 + c);
        }
        __syncthreads();
#pragma unroll
        for (int k = 0; k < 16; k++) {
            float4 a0 = *(const float4*)&As[k][ty * 4];
            float4 a1 = *(const float4*)&As[k][ty * 4 + 64];
            float4 b0 = *(const float4*)&Bs[k][tx * 4];
            float4 b1 = *(const float4*)&Bs[k][tx * 4 + 64];
            float av[8] = {a0.x, a0.y, a0.z, a0.w, a1.x, a1.y, a1.z, a1.w};
            float bv[8] = {b0.x, b0.y, b0.z, b0.w, b1.x, b1.y, b1.z, b1.w};
#pragma unroll
            for (int i = 0; i < 8; i++)
#pragma unroll
                for (int j = 0; j < 8; j++)
                    acc[i][j] = fmaf(av[i], bv[j], acc[i][j]);
        }
        __syncthreads();
    }
    // epilogue: scale by dinv[row], store
#pragma unroll
    for (int half = 0; half < 2; half++) {
#pragma unroll
        for (int i = 0; i < 4; i++) {
            int grow = row0 + half * 64 + ty * 4 + i;
            if (grow >= M) continue;
            float s = dinv[grow];
            int ai = half * 4 + i;
#pragma unroll
            for (int ch = 0; ch < 2; ch++) {
                float4 v;
                v.x = acc[ai][ch * 4 + 0] * s;
                v.y = acc[ai][ch * 4 + 1] * s;
                v.z = acc[ai][ch * 4 + 2] * s;
                v.w = acc[ai][ch * 4 + 3] * s;
                *(float4*)(C + (size_t)grow * N + col0 + ch * 64 + tx * 4) = v;
            }
        }
    }
}

// -------- edge scatter: acc[dst] += hs[src]  (one warp per edge, vector atomics) --------
template <int F>
__global__ void k_scatter(const void* __restrict__ ei,
                          const float* __restrict__ hs, float* __restrict__ acc, int E)
{
    int gw = (blockIdx.x * blockDim.x + threadIdx.x) >> 5;
    int lane = threadIdx.x & 31;
    if (gw >= E) return;
    int is64 = g_is64;
    long long s = edge_at(ei, gw, is64);
    long long d = edge_at(ei, E + gw, is64);
    const float4* sp = (const float4*)(hs + (size_t)s * F);
    float4* dp = (float4*)(acc + (size_t)d * F);
#pragma unroll
    for (int i = 0; i < F / 128; i++) {
        float4 v = sp[lane + 32 * i];
        asm volatile("red.global.add.v4.f32 [%0], {%1,%2,%3,%4};"
                     :: "l"(dp + lane + 32 * i),
                        "f"(v.x), "f"(v.y), "f"(v.z), "f"(v.w)
                     : "memory");
    }
}

// -------- pointwise epilogue: out = dinv*(acc + hs) + bias, optional relu --------
template <int F, bool RELU>
__global__ void k_post(const float* __restrict__ acc, const float* __restrict__ hs,
                       const float* __restrict__ dinv, const float* __restrict__ bias,
                       float* __restrict__ out, int n)
{
    int i = blockIdx.x * blockDim.x + threadIdx.x;   // over n*F/4 float4s
    if (i >= n * (F / 4)) return;
    int row = i / (F / 4);
    int cb = (i % (F / 4)) * 4;
    float s = dinv[row];
    float4 a = ((const float4*)acc)[i];
    float4 h = ((const float4*)hs)[i];
    float4 b = *(const float4*)(bias + cb);
    float4 o;
    o.x = s * (a.x + h.x) + b.x;
    o.y = s * (a.y + h.y) + b.y;
    o.z = s * (a.z + h.z) + b.z;
    o.w = s * (a.w + h.w) + b.w;
    if (RELU) {
        o.x = fmaxf(o.x, 0.f); o.y = fmaxf(o.y, 0.f);
        o.z = fmaxf(o.z, 0.f); o.w = fmaxf(o.w, 0.f);
    }
    ((float4*)out)[i] = o;
}

extern "C" void kernel_launch(void* const* d_in, const int* in_sizes, int n_in,
                              void* d_out, int out_size)
{
    const float* x  = (const float*)d_in[0];
    const void*  ei = d_in[1];
    const float* W1 = (const float*)d_in[2];
    const float* b1 = (const float*)d_in[3];
    const float* W2 = (const float*)d_in[4];
    const float* b2 = (const float*)d_in[5];
    const int E = in_sizes[1] / 2;
    const int n = NN;

    float *deg, *dinv, *hs1, *acc1, *hs2, *acc2;
    cudaGetSymbolAddress((void**)&deg,  g_deg);
    cudaGetSymbolAddress((void**)&dinv, g_dinv);
    cudaGetSymbolAddress((void**)&hs1,  g_hs1);
    cudaGetSymbolAddress((void**)&acc1, g_acc1);
    cudaGetSymbolAddress((void**)&hs2,  g_hs2);
    cudaGetSymbolAddress((void**)&acc2, g_acc2);

    // dtype sniff (int64 vs int32 edge_index)
    k_detect<<<1, 256>>>((const int*)ei, 8192);

    // init: deg = 1 (self loops), acc1/acc2 = 0
    k_setones<<<(n + 255) / 256, 256>>>(deg, n);
    k_zero4<<<(n * (F1 / 4) + 255) / 256, 256>>>((float4*)acc1, n * (F1 / 4));
    k_zero4<<<(n * (F2 / 4) + 255) / 256, 256>>>((float4*)acc2, n * (F2 / 4));

    // degrees + dinv
    k_edgedeg<<<(E + 255) / 256, 256>>>(ei, deg, E);
    k_rsqrt<<<(n + 255) / 256, 256>>>(deg, dinv, n);

    // ---- layer 1 ----
    {
        dim3 grid(F1 / 128, (n + 127) / 128);
        k_gemm<<<grid, 256>>>(x, W1, dinv, hs1, n, F1, 256);
    }
    {
        long long tw = (long long)E * 32;
        k_scatter<F1><<<(unsigned)((tw + 255) / 256), 256>>>(ei, hs1, acc1, E);
    }
    // h1 = relu(dinv*(acc1+hs1)+b1), written in-place into hs1
    k_post<F1, true><<<(n * (F1 / 4) + 255) / 256, 256>>>(acc1, hs1, dinv, b1, hs1, n);

    // ---- layer 2 ----
    {
        dim3 grid(F2 / 128, (n + 127) / 128);
        k_gemm<<<grid, 256>>>(hs1, W2, dinv, hs2, n, F2, 256);
    }
    {
        long long tw = (long long)E * 32;
        k_scatter<F2><<<(unsigned)((tw + 255) / 256), 256>>>(ei, hs2, acc2, E);
    }
    k_post<F2, false><<<(n * (F2 / 4) + 255) / 256, 256>>>(acc2, hs2, dinv, b2, (float*)d_out, n);
}

// round 2
// speedup vs baseline: 1.5241x; 1.5241x over previous
#include <cuda_runtime.h>

#define NN 50000
#define F1 256
#define F2 128
#define EMAX 2000000

// -------- scratch (static device globals; no allocation) --------
__device__ int g_deg[NN];
__device__ int g_off[NN + 1];
__device__ int g_cur[NN];
__device__ int g_srcs[EMAX];
__device__ __align__(16) float g_dinv[NN];
__device__ __align__(16) float g_hs1[(size_t)NN * F1];   // (x@W1)*dinv
__device__ __align__(16) float g_h1[(size_t)NN * F1];    // relu'd layer-1 output
__device__ __align__(16) float g_hs2[(size_t)NN * F2];   // (h1@W2)*dinv
__device__ int g_is64;

// -------- edge dtype detection (int64 vs int32) --------
// int64 values < 50000 -> every odd 32-bit word is 0; impossible for 4096
// consecutive random int32 in [0, 50000).
__global__ void k_detect(const int* __restrict__ w, int nwords) {
    __shared__ int ok;
    if (threadIdx.x == 0) ok = 1;
    __syncthreads();
    for (int i = threadIdx.x; i < nwords / 2; i += blockDim.x)
        if (w[2 * i + 1] != 0) ok = 0;   // benign race
    __syncthreads();
    if (threadIdx.x == 0) g_is64 = ok;
}

__device__ __forceinline__ int edge_at(const void* p, int i, int is64) {
    if (is64) return (int)((const long long*)p)[i];
    return ((const int*)p)[i];
}

__global__ void k_zeroint(int* __restrict__ p, int n) {
    int i = blockIdx.x * blockDim.x + threadIdx.x;
    if (i < n) p[i] = 0;
}

// -------- per-dst edge degree (int atomics) --------
__global__ void k_edgedeg(const void* __restrict__ ei, int* __restrict__ deg, int E) {
    int i = blockIdx.x * blockDim.x + threadIdx.x;
    if (i >= E) return;
    int d = edge_at(ei, E + i, g_is64);
    atomicAdd(deg + d, 1);
}

// -------- single-block exclusive scan over deg -> off, cur --------
__global__ void k_scan(const int* __restrict__ deg, int* __restrict__ off,
                       int* __restrict__ cur) {
    const int CH = (NN + 1023) / 1024;
    int t = threadIdx.x;
    int base = t * CH;
    int s = 0;
    for (int i = 0; i < CH; i++) {
        int idx = base + i;
        if (idx < NN) s += deg[idx];
    }
    __shared__ int sh[1024];
    sh[t] = s;
    __syncthreads();
    for (int d = 1; d < 1024; d <<= 1) {
        int v = 0;
        if (t >= d) v = sh[t - d];
        __syncthreads();
        if (t >= d) sh[t] += v;
        __syncthreads();
    }
    int run = sh[t] - s;   // exclusive prefix
    for (int i = 0; i < CH; i++) {
        int idx = base + i;
        if (idx < NN) { off[idx] = run; cur[idx] = run; run += deg[idx]; }
    }
    if (t == 1023) off[NN] = sh[1023];
}

// -------- dinv = rsqrt(deg + 1)   (+1 = self loop) --------
__global__ void k_rsqrt(const int* __restrict__ deg, float* __restrict__ dinv, int n) {
    int i = blockIdx.x * blockDim.x + threadIdx.x;
    if (i < n) dinv[i] = rsqrtf((float)deg[i] + 1.0f);
}

// -------- counting-sort bucket fill: srcs sorted by dst --------
__global__ void k_bucket(const void* __restrict__ ei, int* __restrict__ cur,
                         int* __restrict__ srcs, int E) {
    int i = blockIdx.x * blockDim.x + threadIdx.x;
    if (i >= E) return;
    int is64 = g_is64;
    int s = edge_at(ei, i, is64);
    int d = edge_at(ei, E + i, is64);
    int p = atomicAdd(cur + d, 1);
    srcs[p] = s;
}

// -------- GEMM: C[row] = (A@B)[row] * dinv[row]   (A:[M,K] B:[K,N] row-major) --------
__global__ __launch_bounds__(256) void k_gemm(
    const float* __restrict__ A, const float* __restrict__ B,
    const float* __restrict__ dinv, float* __restrict__ C,
    int M, int N, int K)
{
    __shared__ float As[16][128];   // transposed: As[k][m]
    __shared__ float Bs[16][128];
    int tid = threadIdx.x;
    int tx = tid & 15;
    int ty = tid >> 4;
    int row0 = blockIdx.y * 128;
    int col0 = blockIdx.x * 128;

    float acc[8][8];
#pragma unroll
    for (int i = 0; i < 8; i++)
#pragma unroll
        for (int j = 0; j < 8; j++) acc[i][j] = 0.f;

    for (int kt = 0; kt < K; kt += 16) {
#pragma unroll
        for (int i = 0; i < 2; i++) {
            int f = tid * 2 + i;
            int r = f >> 2;
            int c = (f & 3) * 4;
            float4 v = make_float4(0.f, 0.f, 0.f, 0.f);
            int grow = row0 + r;
            if (grow < M) v = *(const float4*)(A + (size_t)grow * K + kt + c);
            As[c + 0][r] = v.x; As[c + 1][r] = v.y;
            As[c + 2][r] = v.z; As[c + 3][r] = v.w;
        }
#pragma unroll
        for (int i = 0; i < 2; i++) {
            int f = tid * 2 + i;
            int r = f >> 5;
            int c = (f & 31) * 4;
            *(float4*)&Bs[r][c] = *(const float4*)(B + (size_t)(kt + r) * N + col0 + c);
        }
        __syncthreads();
#pragma unroll
        for (int k = 0; k < 16; k++) {
            float4 a0 = *(const float4*)&As[k][ty * 4];
            float4 a1 = *(const float4*)&As[k][ty * 4 + 64];
            float4 b0 = *(const float4*)&Bs[k][tx * 4];
            float4 b1 = *(const float4*)&Bs[k][tx * 4 + 64];
            float av[8] = {a0.x, a0.y, a0.z, a0.w, a1.x, a1.y, a1.z, a1.w};
            float bv[8] = {b0.x, b0.y, b0.z, b0.w, b1.x, b1.y, b1.z, b1.w};
#pragma unroll
            for (int i = 0; i < 8; i++)
#pragma unroll
                for (int j = 0; j < 8; j++)
                    acc[i][j] = fmaf(av[i], bv[j], acc[i][j]);
        }
        __syncthreads();
    }
#pragma unroll
    for (int half = 0; half < 2; half++) {
#pragma unroll
        for (int i = 0; i < 4; i++) {
            int grow = row0 + half * 64 + ty * 4 + i;
            if (grow >= M) continue;
            float s = dinv[grow];
            int ai = half * 4 + i;
#pragma unroll
            for (int ch = 0; ch < 2; ch++) {
                float4 v;
                v.x = acc[ai][ch * 4 + 0] * s;
                v.y = acc[ai][ch * 4 + 1] * s;
                v.z = acc[ai][ch * 4 + 2] * s;
                v.w = acc[ai][ch * 4 + 3] * s;
                *(float4*)(C + (size_t)grow * N + col0 + ch * 64 + tx * 4) = v;
            }
        }
    }
}

// -------- CSR gather-reduce + fused epilogue --------
// One warp per (node, 128-feature chunk). out[node] = dinv[node]*(hs[node] +
// sum_{src in bucket} hs[src]) + bias, optional relu. No float atomics.
template <int F, bool RELU>
__global__ __launch_bounds__(256) void k_gather(
    const int* __restrict__ off, const int* __restrict__ srcs,
    const float* __restrict__ hs, const float* __restrict__ dinv,
    const float* __restrict__ bias, float* __restrict__ out)
{
    constexpr int CHUNKS = F / 128;
    constexpr int F4 = F / 4;
    int w = (blockIdx.x * blockDim.x + threadIdx.x) >> 5;
    int lane = threadIdx.x & 31;
    int node = w / CHUNKS;
    int chunk = w - node * CHUNKS;
    if (node >= NN) return;
    int col = chunk * 32 + lane;                     // float4 column
    const float4* base = (const float4*)hs + col;

    float4 a = base[(size_t)node * F4];              // self loop
    int e = off[node], end = off[node + 1];
    for (; e + 4 <= end; e += 4) {
        int s0 = srcs[e], s1 = srcs[e + 1], s2 = srcs[e + 2], s3 = srcs[e + 3];
        float4 v0 = base[(size_t)s0 * F4];
        float4 v1 = base[(size_t)s1 * F4];
        float4 v2 = base[(size_t)s2 * F4];
        float4 v3 = base[(size_t)s3 * F4];
        a.x += v0.x + v1.x + v2.x + v3.x;
        a.y += v0.y + v1.y + v2.y + v3.y;
        a.z += v0.z + v1.z + v2.z + v3.z;
        a.w += v0.w + v1.w + v2.w + v3.w;
    }
    for (; e < end; e++) {
        float4 v = base[(size_t)srcs[e] * F4];
        a.x += v.x; a.y += v.y; a.z += v.z; a.w += v.w;
    }
    float sc = dinv[node];
    float4 b = ((const float4*)bias)[col];
    float4 o;
    o.x = sc * a.x + b.x;
    o.y = sc * a.y + b.y;
    o.z = sc * a.z + b.z;
    o.w = sc * a.w + b.w;
    if (RELU) {
        o.x = fmaxf(o.x, 0.f); o.y = fmaxf(o.y, 0.f);
        o.z = fmaxf(o.z, 0.f); o.w = fmaxf(o.w, 0.f);
    }
    ((float4*)out)[(size_t)node * F4 + col] = o;
}

extern "C" void kernel_launch(void* const* d_in, const int* in_sizes, int n_in,
                              void* d_out, int out_size)
{
    const float* x  = (const float*)d_in[0];
    const void*  ei = d_in[1];
    const float* W1 = (const float*)d_in[2];
    const float* b1 = (const float*)d_in[3];
    const float* W2 = (const float*)d_in[4];
    const float* b2 = (const float*)d_in[5];
    const int E = in_sizes[1] / 2;
    const int n = NN;

    int *deg, *off, *cur, *srcs;
    float *dinv, *hs1, *h1, *hs2;
    cudaGetSymbolAddress((void**)&deg,  g_deg);
    cudaGetSymbolAddress((void**)&off,  g_off);
    cudaGetSymbolAddress((void**)&cur,  g_cur);
    cudaGetSymbolAddress((void**)&srcs, g_srcs);
    cudaGetSymbolAddress((void**)&dinv, g_dinv);
    cudaGetSymbolAddress((void**)&hs1,  g_hs1);
    cudaGetSymbolAddress((void**)&h1,   g_h1);
    cudaGetSymbolAddress((void**)&hs2,  g_hs2);

    // dtype sniff (int64 vs int32 edge_index)
    k_detect<<<1, 256>>>((const int*)ei, 8192);

    // degree -> scan -> dinv -> CSR buckets
    k_zeroint<<<(n + 255) / 256, 256>>>(deg, n);
    k_edgedeg<<<(E + 255) / 256, 256>>>(ei, deg, E);
    k_scan<<<1, 1024>>>(deg, off, cur);
    k_rsqrt<<<(n + 255) / 256, 256>>>(deg, dinv, n);
    k_bucket<<<(E + 255) / 256, 256>>>(ei, cur, srcs, E);

    // ---- layer 1 ----
    {
        dim3 grid(F1 / 128, (n + 127) / 128);
        k_gemm<<<grid, 256>>>(x, W1, dinv, hs1, n, F1, 256);
    }
    {
        int warps = n * (F1 / 128);
        k_gather<F1, true><<<(warps * 32 + 255) / 256, 256>>>(off, srcs, hs1, dinv, b1, h1);
    }

    // ---- layer 2 ----
    {
        dim3 grid(F2 / 128, (n + 127) / 128);
        k_gemm<<<grid, 256>>>(h1, W2, dinv, hs2, n, F2, 256);
    }
    {
        int warps = n * (F2 / 128);
        k_gather<F2, false><<<(warps * 32 + 255) / 256, 256>>>(off, srcs, hs2, dinv, b2, (float*)d_out);
    }
}

// round 3
// speedup vs baseline: 1.8607x; 1.2209x over previous
#include <cuda_runtime.h>

#define NN 50000
#define F1 256
#define F2 128
#define EMAX 2000000
#define SCAN_B 1024
#define NBLK ((NN + SCAN_B - 1) / SCAN_B)   // 49

// -------- scratch (static device globals; no allocation) --------
__device__ int g_deg[NN];
__device__ int g_off[NN + 1];
__device__ int g_cur[NN];
__device__ int g_bsum[NBLK];
__device__ int g_srcs[EMAX];
__device__ __align__(16) float g_dinv[NN];
__device__ __align__(16) float g_hs1[(size_t)NN * F1];
__device__ __align__(16) float g_h1[(size_t)NN * F1];
__device__ __align__(16) float g_hs2[(size_t)NN * F2];
__device__ int g_is64;

// -------- packed f32x2 helpers (FFMA2 — only reachable via PTX) --------
#define PACKF2(d, lo, hi) \
    asm("mov.b64 %0, {%1, %2};" : "=l"(d) : "f"(lo), "f"(hi))
#define UNPACKF2(lo, hi, s) \
    asm("mov.b64 {%0, %1}, %2;" : "=f"(lo), "=f"(hi) : "l"(s))
#define FMAF2(acc, a, b) \
    asm("fma.rn.f32x2 %0, %1, %2, %0;" : "+l"(acc) : "l"(a), "l"(b))

// -------- edge dtype detection (int64 vs int32) --------
__global__ void k_detect(const int* __restrict__ w, int nwords) {
    __shared__ int ok;
    if (threadIdx.x == 0) ok = 1;
    __syncthreads();
    for (int i = threadIdx.x; i < nwords / 2; i += blockDim.x)
        if (w[2 * i + 1] != 0) ok = 0;   // benign race
    __syncthreads();
    if (threadIdx.x == 0) g_is64 = ok;
}

__device__ __forceinline__ int edge_at(const void* p, int i, int is64) {
    if (is64) return (int)((const long long*)p)[i];
    return ((const int*)p)[i];
}

__global__ void k_zeroint(int* __restrict__ p, int n) {
    int i = blockIdx.x * blockDim.x + threadIdx.x;
    if (i < n) p[i] = 0;
}

// -------- per-dst edge degree --------
__global__ void k_edgedeg(const void* __restrict__ ei, int* __restrict__ deg, int E) {
    int i = blockIdx.x * blockDim.x + threadIdx.x;
    if (i >= E) return;
    int d = edge_at(ei, E + i, g_is64);
    atomicAdd(deg + d, 1);
}

// -------- 3-phase parallel exclusive scan --------
// Phase 1: per-block exclusive scan of 1024 deg values (written to off), block
// totals to bsum.
__global__ __launch_bounds__(SCAN_B) void k_scan1(
    const int* __restrict__ deg, int* __restrict__ off, int* __restrict__ bsum)
{
    __shared__ int sh[SCAN_B];
    int t = threadIdx.x;
    int idx = blockIdx.x * SCAN_B + t;
    int v = (idx < NN) ? deg[idx] : 0;
    sh[t] = v;
    __syncthreads();
#pragma unroll
    for (int d = 1; d < SCAN_B; d <<= 1) {
        int u = 0;
        if (t >= d) u = sh[t - d];
        __syncthreads();
        if (t >= d) sh[t] += u;
        __syncthreads();
    }
    if (idx < NN) off[idx] = sh[t] - v;   // exclusive within block
    if (t == SCAN_B - 1) bsum[blockIdx.x] = sh[t];
}
// Phase 2: exclusive scan of NBLK block totals (1 warp-ish block).
__global__ void k_scan2(int* __restrict__ bsum, int* __restrict__ off_last) {
    __shared__ int sh[64];
    int t = threadIdx.x;
    int v = (t < NBLK) ? bsum[t] : 0;
    sh[t] = v;
    __syncthreads();
#pragma unroll
    for (int d = 1; d < 64; d <<= 1) {
        int u = 0;
        if (t >= d) u = sh[t - d];
        __syncthreads();
        if (t >= d) sh[t] += u;
        __syncthreads();
    }
    if (t < NBLK) bsum[t] = sh[t] - v;    // exclusive carry per block
    if (t == 63) *off_last = sh[63];      // off[NN] = total E
}
// Phase 3: add block carry; fill cur; dinv.
__global__ void k_scan3(int* __restrict__ off, int* __restrict__ cur,
                        const int* __restrict__ bsum, const int* __restrict__ deg,
                        float* __restrict__ dinv)
{
    int idx = blockIdx.x * SCAN_B + threadIdx.x;
    if (idx >= NN) return;
    int o = off[idx] + bsum[blockIdx.x];
    off[idx] = o;
    cur[idx] = o;
    dinv[idx] = rsqrtf((float)deg[idx] + 1.0f);   // +1 self loop
}

// -------- counting-sort bucket fill --------
__global__ void k_bucket(const void* __restrict__ ei, int* __restrict__ cur,
                         int* __restrict__ srcs, int E) {
    int i = blockIdx.x * blockDim.x + threadIdx.x;
    if (i >= E) return;
    int is64 = g_is64;
    int s = edge_at(ei, i, is64);
    int d = edge_at(ei, E + i, is64);
    int p = atomicAdd(cur + d, 1);
    srcs[p] = s;
}

// -------- GEMM with packed f32x2 FMA: C[row] = (A@B)[row] * dinv[row] --------
// 128x128 tile, BK=16, 256 threads, 8 rows x 4 col-pairs per thread.
__global__ __launch_bounds__(256) void k_gemm(
    const float* __restrict__ A, const float* __restrict__ B,
    const float* __restrict__ dinv, float* __restrict__ C,
    int M, int N, int K)
{
    __shared__ float As[16][128];   // transposed: As[k][m]
    __shared__ float Bs[16][128];
    int tid = threadIdx.x;
    int tx = tid & 15;
    int ty = tid >> 4;
    int row0 = blockIdx.y * 128;
    int col0 = blockIdx.x * 128;

    unsigned long long acc[8][4];   // [row][col-pair], packed f32x2
#pragma unroll
    for (int i = 0; i < 8; i++)
#pragma unroll
        for (int j = 0; j < 4; j++) acc[i][j] = 0ULL;

    for (int kt = 0; kt < K; kt += 16) {
#pragma unroll
        for (int i = 0; i < 2; i++) {
            int f = tid * 2 + i;
            int r = f >> 2;
            int c = (f & 3) * 4;
            float4 v = make_float4(0.f, 0.f, 0.f, 0.f);
            int grow = row0 + r;
            if (grow < M) v = *(const float4*)(A + (size_t)grow * K + kt + c);
            As[c + 0][r] = v.x; As[c + 1][r] = v.y;
            As[c + 2][r] = v.z; As[c + 3][r] = v.w;
        }
#pragma unroll
        for (int i = 0; i < 2; i++) {
            int f = tid * 2 + i;
            int r = f >> 5;
            int c = (f & 31) * 4;
            *(float4*)&Bs[r][c] = *(const float4*)(B + (size_t)(kt + r) * N + col0 + c);
        }
        __syncthreads();
#pragma unroll
        for (int k = 0; k < 16; k++) {
            float4 a0 = *(const float4*)&As[k][ty * 4];
            float4 a1 = *(const float4*)&As[k][ty * 4 + 64];
            float4 b0 = *(const float4*)&Bs[k][tx * 4];
            float4 b1 = *(const float4*)&Bs[k][tx * 4 + 64];
            unsigned long long bp[4];
            PACKF2(bp[0], b0.x, b0.y);
            PACKF2(bp[1], b0.z, b0.w);
            PACKF2(bp[2], b1.x, b1.y);
            PACKF2(bp[3], b1.z, b1.w);
            float av[8] = {a0.x, a0.y, a0.z, a0.w, a1.x, a1.y, a1.z, a1.w};
#pragma unroll
            for (int i = 0; i < 8; i++) {
                unsigned long long ap;
                PACKF2(ap, av[i], av[i]);
#pragma unroll
                for (int j = 0; j < 4; j++)
                    FMAF2(acc[i][j], ap, bp[j]);
            }
        }
        __syncthreads();
    }
#pragma unroll
    for (int half = 0; half < 2; half++) {
#pragma unroll
        for (int i = 0; i < 4; i++) {
            int grow = row0 + half * 64 + ty * 4 + i;
            if (grow >= M) continue;
            float s = dinv[grow];
            int ai = half * 4 + i;
#pragma unroll
            for (int ch = 0; ch < 2; ch++) {
                float4 v;
                UNPACKF2(v.x, v.y, acc[ai][ch * 2 + 0]);
                UNPACKF2(v.z, v.w, acc[ai][ch * 2 + 1]);
                v.x *= s; v.y *= s; v.z *= s; v.w *= s;
                *(float4*)(C + (size_t)grow * N + col0 + ch * 64 + tx * 4) = v;
            }
        }
    }
}

// -------- CSR gather-reduce + fused epilogue --------
template <int F, bool RELU>
__global__ __launch_bounds__(256) void k_gather(
    const int* __restrict__ off, const int* __restrict__ srcs,
    const float* __restrict__ hs, const float* __restrict__ dinv,
    const float* __restrict__ bias, float* __restrict__ out)
{
    constexpr int CHUNKS = F / 128;
    constexpr int F4 = F / 4;
    int w = (blockIdx.x * blockDim.x + threadIdx.x) >> 5;
    int lane = threadIdx.x & 31;
    int node = w / CHUNKS;
    int chunk = w - node * CHUNKS;
    if (node >= NN) return;
    int col = chunk * 32 + lane;
    const float4* base = (const float4*)hs + col;

    float4 a = base[(size_t)node * F4];              // self loop
    int e = off[node], end = off[node + 1];
    for (; e + 4 <= end; e += 4) {
        int s0 = srcs[e], s1 = srcs[e + 1], s2 = srcs[e + 2], s3 = srcs[e + 3];
        float4 v0 = base[(size_t)s0 * F4];
        float4 v1 = base[(size_t)s1 * F4];
        float4 v2 = base[(size_t)s2 * F4];
        float4 v3 = base[(size_t)s3 * F4];
        a.x += v0.x + v1.x + v2.x + v3.x;
        a.y += v0.y + v1.y + v2.y + v3.y;
        a.z += v0.z + v1.z + v2.z + v3.z;
        a.w += v0.w + v1.w + v2.w + v3.w;
    }
    for (; e < end; e++) {
        float4 v = base[(size_t)srcs[e] * F4];
        a.x += v.x; a.y += v.y; a.z += v.z; a.w += v.w;
    }
    float sc = dinv[node];
    float4 b = ((const float4*)bias)[col];
    float4 o;
    o.x = sc * a.x + b.x;
    o.y = sc * a.y + b.y;
    o.z = sc * a.z + b.z;
    o.w = sc * a.w + b.w;
    if (RELU) {
        o.x = fmaxf(o.x, 0.f); o.y = fmaxf(o.y, 0.f);
        o.z = fmaxf(o.z, 0.f); o.w = fmaxf(o.w, 0.f);
    }
    ((float4*)out)[(size_t)node * F4 + col] = o;
}

extern "C" void kernel_launch(void* const* d_in, const int* in_sizes, int n_in,
                              void* d_out, int out_size)
{
    const float* x  = (const float*)d_in[0];
    const void*  ei = d_in[1];
    const float* W1 = (const float*)d_in[2];
    const float* b1 = (const float*)d_in[3];
    const float* W2 = (const float*)d_in[4];
    const float* b2 = (const float*)d_in[5];
    const int E = in_sizes[1] / 2;
    const int n = NN;

    int *deg, *off, *cur, *srcs, *bsum;
    float *dinv, *hs1, *h1, *hs2;
    cudaGetSymbolAddress((void**)&deg,  g_deg);
    cudaGetSymbolAddress((void**)&off,  g_off);
    cudaGetSymbolAddress((void**)&cur,  g_cur);
    cudaGetSymbolAddress((void**)&srcs, g_srcs);
    cudaGetSymbolAddress((void**)&bsum, g_bsum);
    cudaGetSymbolAddress((void**)&dinv, g_dinv);
    cudaGetSymbolAddress((void**)&hs1,  g_hs1);
    cudaGetSymbolAddress((void**)&h1,   g_h1);
    cudaGetSymbolAddress((void**)&hs2,  g_hs2);

    // dtype sniff
    k_detect<<<1, 256>>>((const int*)ei, 8192);

    // degree -> parallel scan -> dinv -> CSR buckets
    k_zeroint<<<(n + 255) / 256, 256>>>(deg, n);
    k_edgedeg<<<(E + 255) / 256, 256>>>(ei, deg, E);
    k_scan1<<<NBLK, SCAN_B>>>(deg, off, bsum);
    k_scan2<<<1, 64>>>(bsum, off + NN);
    k_scan3<<<NBLK, SCAN_B>>>(off, cur, bsum, deg, dinv);
    k_bucket<<<(E + 255) / 256, 256>>>(ei, cur, srcs, E);

    // ---- layer 1 ----
    {
        dim3 grid(F1 / 128, (n + 127) / 128);
        k_gemm<<<grid, 256>>>(x, W1, dinv, hs1, n, F1, 256);
    }
    {
        int warps = n * (F1 / 128);
        k_gather<F1, true><<<(warps * 32 + 255) / 256, 256>>>(off, srcs, hs1, dinv, b1, h1);
    }

    // ---- layer 2 ----
    {
        dim3 grid(F2 / 128, (n + 127) / 128);
        k_gemm<<<grid, 256>>>(h1, W2, dinv, hs2, n, F2, 256);
    }
    {
        int warps = n * (F2 / 128);
        k_gather<F2, false><<<(warps * 32 + 255) / 256, 256>>>(off, srcs, hs2, dinv, b2, (float*)d_out);
    }
}

// round 5
// speedup vs baseline: 2.0659x; 1.1103x over previous
#include <cuda_runtime.h>
#include <cuda_fp16.h>
#include <cstdint>

#define NN 50000
#define F1 256
#define F2 128
#define EMAX 2000000
#define SCAN_B 1024
#define NBLK ((NN + SCAN_B - 1) / SCAN_B)   // 49

// -------- scratch (static device globals; no allocation) --------
__device__ int g_deg[NN];
__device__ int g_off[NN + 1];
__device__ int g_cur[NN];
__device__ int g_bsum[NBLK];
__device__ int g_srcs[EMAX];
__device__ __align__(16) float g_dinv[NN];
__device__ __align__(16) float  g_hs1[(size_t)NN * F1];   // fp32 (unused by gather, kept for debug)
__device__ __align__(16) __half g_hh1[(size_t)NN * F1];   // fp16 copy of hs1
__device__ __align__(16) float  g_h1[(size_t)NN * F1];    // relu'd layer-1 out (fp32, GEMM2 input)
__device__ __align__(16) float  g_hs2[(size_t)NN * F2];
__device__ __align__(16) __half g_hh2[(size_t)NN * F2];
__device__ int g_is64;

// -------- packed f32x2 helpers (FFMA2) --------
#define PACKF2(d, lo, hi) \
    asm("mov.b64 %0, {%1, %2};" : "=l"(d) : "f"(lo), "f"(hi))
#define UNPACKF2(lo, hi, s) \
    asm("mov.b64 {%0, %1}, %2;" : "=f"(lo), "=f"(hi) : "l"(s))
#define FMAF2(acc, a, b) \
    asm("fma.rn.f32x2 %0, %1, %2, %0;" : "+l"(acc) : "l"(a), "l"(b))

// -------- edge dtype detection (int64 vs int32) --------
__global__ void k_detect(const int* __restrict__ w, int nwords) {
    __shared__ int ok;
    if (threadIdx.x == 0) ok = 1;
    __syncthreads();
    for (int i = threadIdx.x; i < nwords / 2; i += blockDim.x)
        if (w[2 * i + 1] != 0) ok = 0;   // benign race
    __syncthreads();
    if (threadIdx.x == 0) g_is64 = ok;
}
__device__ __forceinline__ int edge_at(const void* p, int i, int is64) {
    if (is64) return (int)((const long long*)p)[i];
    return ((const int*)p)[i];
}

__global__ void k_zeroint(int* __restrict__ p, int n) {
    int i = blockIdx.x * blockDim.x + threadIdx.x;
    if (i < n) p[i] = 0;
}
__global__ void k_edgedeg(const void* __restrict__ ei, int* __restrict__ deg, int E) {
    int i = blockIdx.x * blockDim.x + threadIdx.x;
    if (i >= E) return;
    int d = edge_at(ei, E + i, g_is64);
    atomicAdd(deg + d, 1);
}

// -------- 3-phase parallel exclusive scan --------
__global__ __launch_bounds__(SCAN_B) void k_scan1(
    const int* __restrict__ deg, int* __restrict__ off, int* __restrict__ bsum)
{
    __shared__ int sh[SCAN_B];
    int t = threadIdx.x;
    int idx = blockIdx.x * SCAN_B + t;
    int v = (idx < NN) ? deg[idx] : 0;
    sh[t] = v;
    __syncthreads();
#pragma unroll
    for (int d = 1; d < SCAN_B; d <<= 1) {
        int u = 0;
        if (t >= d) u = sh[t - d];
        __syncthreads();
        if (t >= d) sh[t] += u;
        __syncthreads();
    }
    if (idx < NN) off[idx] = sh[t] - v;
    if (t == SCAN_B - 1) bsum[blockIdx.x] = sh[t];
}
__global__ void k_scan2(int* __restrict__ bsum, int* __restrict__ off_last) {
    __shared__ int sh[64];
    int t = threadIdx.x;
    int v = (t < NBLK) ? bsum[t] : 0;
    sh[t] = v;
    __syncthreads();
#pragma unroll
    for (int d = 1; d < 64; d <<= 1) {
        int u = 0;
        if (t >= d) u = sh[t - d];
        __syncthreads();
        if (t >= d) sh[t] += u;
        __syncthreads();
    }
    if (t < NBLK) bsum[t] = sh[t] - v;
    if (t == 63) *off_last = sh[63];
}
__global__ void k_scan3(int* __restrict__ off, int* __restrict__ cur,
                        const int* __restrict__ bsum, const int* __restrict__ deg,
                        float* __restrict__ dinv)
{
    int idx = blockIdx.x * SCAN_B + threadIdx.x;
    if (idx >= NN) return;
    int o = off[idx] + bsum[blockIdx.x];
    off[idx] = o;
    cur[idx] = o;
    dinv[idx] = rsqrtf((float)deg[idx] + 1.0f);
}

__global__ void k_bucket(const void* __restrict__ ei, int* __restrict__ cur,
                         int* __restrict__ srcs, int E) {
    int i = blockIdx.x * blockDim.x + threadIdx.x;
    if (i >= E) return;
    int is64 = g_is64;
    int s = edge_at(ei, i, is64);
    int d = edge_at(ei, E + i, is64);
    int p = atomicAdd(cur + d, 1);
    srcs[p] = s;
}

// -------- GEMM (FFMA2): C = (A@B)*dinv[row], plus fp16 copy Ch --------
__global__ __launch_bounds__(256) void k_gemm(
    const float* __restrict__ A, const float* __restrict__ B,
    const float* __restrict__ dinv, float* __restrict__ C,
    __half* __restrict__ Ch, int M, int N, int K)
{
    __shared__ float As[16][128];   // transposed: As[k][m]
    __shared__ float Bs[16][128];
    int tid = threadIdx.x;
    int tx = tid & 15;
    int ty = tid >> 4;
    int row0 = blockIdx.y * 128;
    int col0 = blockIdx.x * 128;

    unsigned long long acc[8][4];
#pragma unroll
    for (int i = 0; i < 8; i++)
#pragma unroll
        for (int j = 0; j < 4; j++) acc[i][j] = 0ULL;

    for (int kt = 0; kt < K; kt += 16) {
#pragma unroll
        for (int i = 0; i < 2; i++) {
            int f = tid * 2 + i;
            int r = f >> 2;
            int c = (f & 3) * 4;
            float4 v = make_float4(0.f, 0.f, 0.f, 0.f);
            int grow = row0 + r;
            if (grow < M) v = *(const float4*)(A + (size_t)grow * K + kt + c);
            As[c + 0][r] = v.x; As[c + 1][r] = v.y;
            As[c + 2][r] = v.z; As[c + 3][r] = v.w;
        }
#pragma unroll
        for (int i = 0; i < 2; i++) {
            int f = tid * 2 + i;
            int r = f >> 5;
            int c = (f & 31) * 4;
            *(float4*)&Bs[r][c] = *(const float4*)(B + (size_t)(kt + r) * N + col0 + c);
        }
        __syncthreads();
#pragma unroll
        for (int k = 0; k < 16; k++) {
            float4 a0 = *(const float4*)&As[k][ty * 4];
            float4 a1 = *(const float4*)&As[k][ty * 4 + 64];
            float4 b0 = *(const float4*)&Bs[k][tx * 4];
            float4 b1 = *(const float4*)&Bs[k][tx * 4 + 64];
            unsigned long long bp[4];
            PACKF2(bp[0], b0.x, b0.y);
            PACKF2(bp[1], b0.z, b0.w);
            PACKF2(bp[2], b1.x, b1.y);
            PACKF2(bp[3], b1.z, b1.w);
            float av[8] = {a0.x, a0.y, a0.z, a0.w, a1.x, a1.y, a1.z, a1.w};
#pragma unroll
            for (int i = 0; i < 8; i++) {
                unsigned long long ap;
                PACKF2(ap, av[i], av[i]);
#pragma unroll
                for (int j = 0; j < 4; j++)
                    FMAF2(acc[i][j], ap, bp[j]);
            }
        }
        __syncthreads();
    }
#pragma unroll
    for (int half = 0; half < 2; half++) {
#pragma unroll
        for (int i = 0; i < 4; i++) {
            int grow = row0 + half * 64 + ty * 4 + i;
            if (grow >= M) continue;
            float s = dinv[grow];
            int ai = half * 4 + i;
#pragma unroll
            for (int ch = 0; ch < 2; ch++) {
                float4 v;
                UNPACKF2(v.x, v.y, acc[ai][ch * 2 + 0]);
                UNPACKF2(v.z, v.w, acc[ai][ch * 2 + 1]);
                v.x *= s; v.y *= s; v.z *= s; v.w *= s;
                size_t o = (size_t)grow * N + col0 + ch * 64 + tx * 4;
                *(float4*)(C + o) = v;
                __half2 h0 = __floats2half2_rn(v.x, v.y);
                __half2 h1 = __floats2half2_rn(v.z, v.w);
                uint2 hp;
                hp.x = *(uint32_t*)&h0;
                hp.y = *(uint32_t*)&h1;
                *(uint2*)(Ch + o) = hp;
            }
        }
    }
}

// -------- CSR gather-reduce over fp16 features, fp32 accumulate --------
// One warp per node. FH halfs per lane (8 -> F=256 via 16B loads, 4 -> F=128 via 8B).
template <int FH, bool RELU>
__global__ __launch_bounds__(256) void k_gather_h(
    const int* __restrict__ off, const int* __restrict__ srcs,
    const __half* __restrict__ hsh, const float* __restrict__ dinv,
    const float* __restrict__ bias, float* __restrict__ out)
{
    constexpr int F = 32 * FH;
    int node = (blockIdx.x * blockDim.x + threadIdx.x) >> 5;
    int lane = threadIdx.x & 31;
    if (node >= NN) return;
    const __half* base = hsh + lane * FH;

    float acc[FH];
#pragma unroll
    for (int j = 0; j < FH; j++) acc[j] = 0.f;

    auto accum = [&](int s) {
        const __half* p = base + (size_t)s * F;
        if (FH == 8) {
            uint4 v = *(const uint4*)p;
            float2 f;
            f = __half22float2(*(__half2*)&v.x); acc[0] += f.x; acc[1] += f.y;
            f = __half22float2(*(__half2*)&v.y); acc[2] += f.x; acc[3] += f.y;
            f = __half22float2(*(__half2*)&v.z); acc[4] += f.x; acc[5] += f.y;
            f = __half22float2(*(__half2*)&v.w); acc[6] += f.x; acc[7] += f.y;
        } else {
            uint2 v = *(const uint2*)p;
            float2 f;
            f = __half22float2(*(__half2*)&v.x); acc[0] += f.x; acc[1] += f.y;
            f = __half22float2(*(__half2*)&v.y); acc[2] += f.x; acc[3] += f.y;
        }
    };

    accum(node);                                   // self loop
    int e = off[node], end = off[node + 1];
    for (; e + 4 <= end; e += 4) {
        int s0 = srcs[e], s1 = srcs[e + 1], s2 = srcs[e + 2], s3 = srcs[e + 3];
        accum(s0); accum(s1); accum(s2); accum(s3);
    }
    for (; e < end; e++) accum(srcs[e]);

    float sc = dinv[node];
    float* dst = out + (size_t)node * F + lane * FH;
    const float* bp = bias + lane * FH;
#pragma unroll
    for (int j = 0; j < FH; j += 4) {
        float4 b = *(const float4*)(bp + j);
        float4 o;
        o.x = sc * acc[j + 0] + b.x;
        o.y = sc * acc[j + 1] + b.y;
        o.z = sc * acc[j + 2] + b.z;
        o.w = sc * acc[j + 3] + b.w;
        if (RELU) {
            o.x = fmaxf(o.x, 0.f); o.y = fmaxf(o.y, 0.f);
            o.z = fmaxf(o.z, 0.f); o.w = fmaxf(o.w, 0.f);
        }
        *(float4*)(dst + j) = o;
    }
}

extern "C" void kernel_launch(void* const* d_in, const int* in_sizes, int n_in,
                              void* d_out, int out_size)
{
    const float* x  = (const float*)d_in[0];
    const void*  ei = d_in[1];
    const float* W1 = (const float*)d_in[2];
    const float* b1 = (const float*)d_in[3];
    const float* W2 = (const float*)d_in[4];
    const float* b2 = (const float*)d_in[5];
    const int E = in_sizes[1] / 2;
    const int n = NN;

    int *deg, *off, *cur, *srcs, *bsum;
    float *dinv, *hs1, *h1, *hs2;
    __half *hh1, *hh2;
    cudaGetSymbolAddress((void**)&deg,  g_deg);
    cudaGetSymbolAddress((void**)&off,  g_off);
    cudaGetSymbolAddress((void**)&cur,  g_cur);
    cudaGetSymbolAddress((void**)&srcs, g_srcs);
    cudaGetSymbolAddress((void**)&bsum, g_bsum);
    cudaGetSymbolAddress((void**)&dinv, g_dinv);
    cudaGetSymbolAddress((void**)&hs1,  g_hs1);
    cudaGetSymbolAddress((void**)&hh1,  g_hh1);
    cudaGetSymbolAddress((void**)&h1,   g_h1);
    cudaGetSymbolAddress((void**)&hs2,  g_hs2);
    cudaGetSymbolAddress((void**)&hh2,  g_hh2);

    // dtype sniff
    k_detect<<<1, 256>>>((const int*)ei, 8192);

    // degree -> parallel scan -> dinv -> CSR buckets
    k_zeroint<<<(n + 255) / 256, 256>>>(deg, n);
    k_edgedeg<<<(E + 255) / 256, 256>>>(ei, deg, E);
    k_scan1<<<NBLK, SCAN_B>>>(deg, off, bsum);
    k_scan2<<<1, 64>>>(bsum, off + NN);
    k_scan3<<<NBLK, SCAN_B>>>(off, cur, bsum, deg, dinv);
    k_bucket<<<(E + 255) / 256, 256>>>(ei, cur, srcs, E);

    // ---- layer 1 ----
    {
        dim3 grid(F1 / 128, (n + 127) / 128);
        k_gemm<<<grid, 256>>>(x, W1, dinv, hs1, hh1, n, F1, 256);
    }
    k_gather_h<8, true><<<(n * 32 + 255) / 256, 256>>>(off, srcs, hh1, dinv, b1, h1);

    // ---- layer 2 ----
    {
        dim3 grid(F2 / 128, (n + 127) / 128);
        k_gemm<<<grid, 256>>>(h1, W2, dinv, hs2, hh2, n, F2, 256);
    }
    k_gather_h<4, false><<<(n * 32 + 255) / 256, 256>>>(off, srcs, hh2, dinv, b2, (float*)d_out);
}